// round 1
// baseline (speedup 1.0000x reference)
#include <cuda_runtime.h>
#include <cuda_bf16.h>

// ---------------- problem constants ----------------
#define N0 6912      // 48*48*3
#define N1 27648     // 96*96*3
#define N2 110592    // 192*192*3
#define NTOT 145152  // N0+N1+N2
#define TILES 284    // ceil(NTOT/512)
#define SCANL (256 * TILES)  // 72704
#define MAXB 100

// ---------------- scratch (device globals; no allocation) ----------------
__device__ float4   g_bbox[NTOT];
__device__ float    g_conf[NTOT];
__device__ int      g_cls[NTOT];
__device__ unsigned g_keysA[NTOT], g_valsA[NTOT];
__device__ unsigned g_keysB[NTOT], g_valsB[NTOT];
__device__ unsigned g_counts[SCANL];
__device__ unsigned g_maxp, g_minp;

// order-preserving float<->uint encodings
__device__ __forceinline__ unsigned enc_ord(float f) {
    unsigned u = __float_as_uint(f);
    return (u & 0x80000000u) ? ~u : (u ^ 0x80000000u);
}
__device__ __forceinline__ float dec_ord(unsigned o) {
    unsigned u = (o & 0x80000000u) ? (o ^ 0x80000000u) : ~o;
    return __uint_as_float(u);
}

__device__ __forceinline__ bool iou_gt_half(float4 a, float areaA, float4 b, float areaB) {
    float iw = fminf(a.z, b.z) - fmaxf(a.x, b.x); iw = fmaxf(iw, 0.0f);
    float ih = fminf(a.w, b.w) - fmaxf(a.y, b.y); ih = fmaxf(ih, 0.0f);
    float inter = iw * ih;
    float iou = __fdiv_rn(inter, areaA + areaB - inter);
    return iou > 0.5f;
}

// ---------------- K0: init ----------------
__global__ void init_kernel() {
    g_maxp = 0u;           // < enc of any finite float
    g_minp = 0xFFFFFFFFu;  // > enc of any finite float
}

// ---------------- K1: decode (one warp per box) ----------------
__global__ void decode_kernel(const float* __restrict__ g0,
                              const float* __restrict__ g1,
                              const float* __restrict__ g2,
                              const float* __restrict__ anch) {
    int gw = (blockIdx.x * blockDim.x + threadIdx.x) >> 5;
    int lane = threadIdx.x & 31;
    int wid = threadIdx.x >> 5;
    bool active = gw < NTOT;

    float bv = -3.4e38f;
    int bi = 0;

    if (active) {
        const float* src; int H; int local; int abase;
        if (gw < N0)            { src = g0; H = 48;  local = gw;            abase = 12; }
        else if (gw < N0 + N1)  { src = g1; H = 96;  local = gw - N0;       abase = 6;  }
        else                    { src = g2; H = 192; local = gw - N0 - N1;  abase = 0;  }
        const float* p = src + (size_t)local * 85;

        // class argmax (first max wins on ties)
        for (int c = lane; c < 80; c += 32) {
            float v = p[5 + c];
            if (v > bv) { bv = v; bi = c; }
        }
        #pragma unroll
        for (int off = 16; off; off >>= 1) {
            float ov = __shfl_xor_sync(0xffffffffu, bv, off);
            int   oi = __shfl_xor_sync(0xffffffffu, bi, off);
            if (ov > bv || (ov == bv && oi < bi)) { bv = ov; bi = oi; }
        }

        if (lane == 0) {
            float x = p[0], y = p[1], wv = p[2], hv = p[3], obj = p[4];
            int a = local % 3;
            int cell = local / 3;
            int cx = cell % H;   // W == H
            int cy = cell / H;
            float aw = anch[abase + a * 2 + 0];
            float ah = anch[abase + a * 2 + 1];
            float bw = expf(wv) * aw;
            float bh = expf(hv) * ah;
            float Hf = (float)H;
            float X = __fdiv_rn(x + (float)cx, Hf);
            float Y = __fdiv_rn(y + (float)cy, Hf);
            g_bbox[gw] = make_float4(X - bw * 0.5f, Y - bh * 0.5f,
                                     X + bw * 0.5f, Y + bh * 0.5f);
            g_conf[gw] = obj;
            g_cls[gw]  = bi;
        }
    }

    // block reduce maxprob -> global atomics
    __shared__ float smax[8], smin[8];
    if (lane == 0) {
        smax[wid] = active ? bv : -3.4e38f;
        smin[wid] = active ? bv :  3.4e38f;
    }
    __syncthreads();
    if (threadIdx.x == 0) {
        float M = smax[0], m = smin[0];
        #pragma unroll
        for (int i = 1; i < 8; ++i) { M = fmaxf(M, smax[i]); m = fminf(m, smin[i]); }
        atomicMax(&g_maxp, enc_ord(M));
        atomicMin(&g_minp, enc_ord(m));
    }
}

// ---------------- K2: scores -> sort keys ----------------
__global__ void key_kernel() {
    int i = blockIdx.x * blockDim.x + threadIdx.x;
    if (i >= NTOT) return;
    float M = dec_ord(g_maxp);
    float m = dec_ord(g_minp);
    float c = g_conf[i];
    float score = fmaxf(c * M, c * m);
    unsigned key;
    if (score > 0.0f) {
        key = ~enc_ord(score);   // descending order key; < 0x80000000 for score>0
    } else {
        key = 0xFFFFFFFFu;       // sentinel, sorts last
    }
    g_keysA[i] = key;
    g_valsA[i] = (unsigned)i;
}

// ---------------- radix sort (4x8-bit LSD, stable) ----------------
__global__ void radix_hist(int pass) {
    const unsigned* keys = (pass & 1) ? g_keysB : g_keysA;
    __shared__ unsigned h[256];
    int t = threadIdx.x;
    if (t < 256) h[t] = 0;
    __syncthreads();
    int p = blockIdx.x * 512 + t;
    if (p < NTOT) {
        unsigned d = (keys[p] >> (pass * 8)) & 0xFFu;
        atomicAdd(&h[d], 1u);
    }
    __syncthreads();
    if (t < 256) g_counts[t * TILES + blockIdx.x] = h[t];
}

__global__ void radix_scan() {
    const int C = (SCANL + 1023) / 1024;  // 71
    int t = threadIdx.x;
    int beg = t * C;
    int end = beg + C; if (end > SCANL) end = SCANL;
    unsigned s = 0;
    for (int i = beg; i < end; ++i) s += g_counts[i];
    __shared__ unsigned part[1024];
    part[t] = s;
    __syncthreads();
    for (int off = 1; off < 1024; off <<= 1) {
        unsigned add = (t >= off) ? part[t - off] : 0u;
        unsigned v = part[t];
        __syncthreads();
        part[t] = v + add;
        __syncthreads();
    }
    unsigned run = (t == 0) ? 0u : part[t - 1];
    for (int i = beg; i < end; ++i) {
        unsigned c = g_counts[i];
        g_counts[i] = run;
        run += c;
    }
}

__global__ void radix_scatter(int pass) {
    const unsigned* kin  = (pass & 1) ? g_keysB : g_keysA;
    const unsigned* vin  = (pass & 1) ? g_valsB : g_valsA;
    unsigned* kout = (pass & 1) ? g_keysA : g_keysB;
    unsigned* vout = (pass & 1) ? g_valsA : g_valsB;

    __shared__ unsigned wc[16][256];
    int t = threadIdx.x;
    int w = t >> 5, lane = t & 31;
    for (int i = t; i < 16 * 256; i += 512) ((unsigned*)wc)[i] = 0u;
    __syncthreads();

    int p = blockIdx.x * 512 + t;
    bool valid = p < NTOT;
    unsigned key = valid ? kin[p] : 0u;
    unsigned d = (key >> (pass * 8)) & 0xFFu;

    unsigned vmask = __ballot_sync(0xffffffffu, valid);
    unsigned mask  = __match_any_sync(0xffffffffu, d) & vmask;
    unsigned lt    = (1u << lane) - 1u;
    unsigned lr    = __popc(mask & lt);
    if (valid && lr == 0) wc[w][d] = __popc(mask);
    __syncthreads();

    if (t < 256) {
        unsigned run = 0;
        #pragma unroll
        for (int ww = 0; ww < 16; ++ww) {
            unsigned c = wc[ww][t];
            wc[ww][t] = run;
            run += c;
        }
    }
    __syncthreads();

    if (valid) {
        unsigned rank = wc[w][d] + lr;
        unsigned dst = g_counts[d * TILES + blockIdx.x] + rank;
        kout[dst] = key;
        vout[dst] = vin[p];
    }
}

// ---------------- final: sorted-order greedy NMS + output ----------------
__global__ void nms_kernel(float* __restrict__ out, int out_size) {
    __shared__ float4 selBox[MAXB];
    __shared__ float  selArea[MAXB];
    __shared__ float  selScore[MAXB];
    __shared__ int    selIdx[MAXB];
    __shared__ float4 candBox[1024];
    __shared__ float  candArea[1024];
    __shared__ float  candScore[1024];
    __shared__ int    candIdx[1024];
    __shared__ unsigned s_ballots[32];
    __shared__ int s_nsel, s_done, s_hitEnd, s_first;

    int tid = threadIdx.x;
    int warp = tid >> 5, lane = tid & 31;

    if (tid == 0) { s_nsel = 0; s_done = 0; s_hitEnd = 0; }
    __syncthreads();

    for (int pos = 0; pos < NTOT; pos += 1024) {
        __syncthreads();  // protect candBox reuse across chunks

        int p = pos + tid;
        bool ok = false;
        float4 mybox = make_float4(0.f, 0.f, 0.f, 0.f);
        float myarea = 0.f, myscore = 0.f;
        int myidx = 0;

        if (p < NTOT) {
            unsigned k = g_keysA[p];
            if (k == 0xFFFFFFFFu) {
                s_hitEnd = 1;
            } else {
                myidx = (int)g_valsA[p];
                mybox = g_bbox[myidx];
                myarea = (mybox.z - mybox.x) * (mybox.w - mybox.y);
                myscore = dec_ord(~k);
                ok = true;
                int n0 = s_nsel;
                for (int s = 0; s < n0; ++s) {
                    if (iou_gt_half(mybox, myarea, selBox[s], selArea[s])) { ok = false; break; }
                }
            }
        } else {
            s_hitEnd = 1;
        }

        candBox[tid] = mybox;
        candArea[tid] = myarea;
        candScore[tid] = myscore;
        candIdx[tid] = myidx;
        bool myAlive = ok;
        __syncthreads();

        // iterative greedy within chunk
        while (true) {
            unsigned bal = __ballot_sync(0xffffffffu, myAlive);
            if (lane == 0) s_ballots[warp] = bal;
            __syncthreads();
            if (tid == 0) {
                int first = -1;
                for (int ww = 0; ww < 32; ++ww) {
                    unsigned b = s_ballots[ww];
                    if (b) { first = (ww << 5) + __ffs(b) - 1; break; }
                }
                s_first = first;
                if (first >= 0) {
                    int n = s_nsel;
                    selBox[n]   = candBox[first];
                    selArea[n]  = candArea[first];
                    selScore[n] = candScore[first];
                    selIdx[n]   = candIdx[first];
                    s_nsel = n + 1;
                    if (n + 1 >= MAXB) s_done = 1;
                }
            }
            __syncthreads();
            int first = s_first;
            if (first < 0) break;
            if (myAlive) {
                if (iou_gt_half(mybox, myarea, candBox[first], candArea[first]))
                    myAlive = false;
            }
            if (s_done) break;
            __syncthreads();
        }

        if (s_done || s_hitEnd) break;
    }

    __syncthreads();
    int nsel = s_nsel;
    for (int i = tid; i < out_size; i += 1024) {
        float v = 0.0f;
        if (i < 400) {
            int j = i >> 2;
            if (j < nsel) v = ((float*)selBox)[i];
        } else if (i < 500) {
            int j = i - 400;
            if (j < nsel) v = selScore[j];
        } else if (i < 600) {
            int j = i - 500;
            if (j < nsel) v = (float)g_cls[selIdx[j]];
        } else if (i == 600) {
            v = (float)nsel;
        }
        out[i] = v;
    }
}

// ---------------- launch ----------------
extern "C" void kernel_launch(void* const* d_in, const int* in_sizes, int n_in,
                              void* d_out, int out_size) {
    const float* g0   = (const float*)d_in[0];
    const float* g1   = (const float*)d_in[1];
    const float* g2   = (const float*)d_in[2];
    const float* anch = (const float*)d_in[3];
    float* out = (float*)d_out;

    init_kernel<<<1, 1>>>();

    // warp per box: 145152 warps, 8 warps/block
    int decode_blocks = (NTOT + 7) / 8;  // 18144
    decode_kernel<<<decode_blocks, 256>>>(g0, g1, g2, anch);

    key_kernel<<<(NTOT + 255) / 256, 256>>>();

    for (int pass = 0; pass < 4; ++pass) {
        radix_hist<<<TILES, 512>>>(pass);
        radix_scan<<<1, 1024>>>();
        radix_scatter<<<TILES, 512>>>(pass);
    }

    nms_kernel<<<1, 1024>>>(out, out_size);
}

// round 2
// speedup vs baseline: 1.2998x; 1.2998x over previous
#include <cuda_runtime.h>
#include <cuda_bf16.h>

// ---------------- problem constants ----------------
#define N0 6912      // 48*48*3
#define N1 27648     // 96*96*3
#define N2 110592    // 192*192*3
#define NTOT 145152
#define NBLK 148
#define NTHR 1024
#define SEG 992      // elements per block-tile (31 warps worth); 148*992 >= NTOT
#define MAXB 100

// ---------------- scratch (device globals) ----------------
__device__ float4   g_bbox[NTOT];
__device__ float    g_conf[NTOT];
__device__ int      g_cls[NTOT];
__device__ unsigned g_keysA[NTOT], g_valsA[NTOT];
__device__ unsigned g_keysB[NTOT], g_valsB[NTOT];
__device__ unsigned g_counts[256 * NBLK];
__device__ unsigned g_digitbase[256];
__device__ unsigned g_maxp, g_minp;
__device__ unsigned g_barcnt, g_barrel;

// order-preserving float<->uint encodings
__device__ __forceinline__ unsigned enc_ord(float f) {
    unsigned u = __float_as_uint(f);
    return (u & 0x80000000u) ? ~u : (u ^ 0x80000000u);
}
__device__ __forceinline__ float dec_ord(unsigned o) {
    unsigned u = (o & 0x80000000u) ? (o ^ 0x80000000u) : ~o;
    return __uint_as_float(u);
}

__device__ __forceinline__ bool iou_gt_half(float4 a, float areaA, float4 b, float areaB) {
    float iw = fminf(a.z, b.z) - fmaxf(a.x, b.x); iw = fmaxf(iw, 0.0f);
    float ih = fminf(a.w, b.w) - fmaxf(a.y, b.y); ih = fmaxf(ih, 0.0f);
    float inter = iw * ih;
    float iou = __fdiv_rn(inter, areaA + areaB - inter);
    return iou > 0.5f;
}

// ---------------- grid barrier (monotonic counter + release word) ----------------
__device__ __forceinline__ void gridbar(unsigned k) {
    __syncthreads();
    if (threadIdx.x == 0) {
        __threadfence();
        unsigned v = atomicAdd(&g_barcnt, 1u);
        if (v + 1u == k * (unsigned)NBLK) {
            __threadfence();
            atomicExch(&g_barrel, k);
        } else {
            unsigned r;
            do {
                asm volatile("ld.acquire.gpu.u32 %0, [%1];" : "=r"(r) : "l"(&g_barrel) : "memory");
            } while (r < k);
        }
    }
    __syncthreads();
}

// ---------------- K0: reset ----------------
__global__ void reset_kernel() {
    g_barcnt = 0u;
    g_barrel = 0u;
    g_maxp = 0u;           // < enc of any finite float
    g_minp = 0xFFFFFFFFu;  // > enc of any finite float
}

// ---------------- K1: persistent mega kernel ----------------
__global__ void __launch_bounds__(NTHR, 1)
mega_kernel(const float* __restrict__ g0,
            const float* __restrict__ g1,
            const float* __restrict__ g2,
            const float* __restrict__ anch,
            float* __restrict__ out, int out_size) {
    __shared__ __align__(16) unsigned char SB[34816];
    __shared__ float s_mx[32], s_mn[32];
    __shared__ unsigned s_ball[32];
    __shared__ int s_nsel, s_done, s_hitEnd, s_first;

    const int tid  = threadIdx.x;
    const int b    = blockIdx.x;
    const int lane = tid & 31;
    const int wid  = tid >> 5;
    unsigned bk = 0;

    // ================= P0: decode (warp per box) =================
    {
        float runM = -3.4e38f, runm = 3.4e38f;
        for (int gw = b * 32 + wid; gw < NTOT; gw += NBLK * 32) {
            const float* src; int H; int local; int abase;
            if (gw < N0)           { src = g0; H = 48;  local = gw;           abase = 12; }
            else if (gw < N0 + N1) { src = g1; H = 96;  local = gw - N0;      abase = 6;  }
            else                   { src = g2; H = 192; local = gw - N0 - N1; abase = 0;  }
            const float* p = src + (size_t)local * 85;

            float bv = -3.4e38f;
            int bi = 0;
            for (int c = lane; c < 80; c += 32) {
                float v = p[5 + c];
                if (v > bv) { bv = v; bi = c; }
            }
            #pragma unroll
            for (int off = 16; off; off >>= 1) {
                float ov = __shfl_xor_sync(0xffffffffu, bv, off);
                int   oi = __shfl_xor_sync(0xffffffffu, bi, off);
                if (ov > bv || (ov == bv && oi < bi)) { bv = ov; bi = oi; }
            }
            runM = fmaxf(runM, bv);
            runm = fminf(runm, bv);

            if (lane == 0) {
                float x = p[0], y = p[1], wv = p[2], hv = p[3], obj = p[4];
                int a = local % 3;
                int cell = local / 3;
                int cx = cell % H;   // W == H
                int cy = cell / H;
                float aw = anch[abase + a * 2 + 0];
                float ah = anch[abase + a * 2 + 1];
                float bw = expf(wv) * aw;
                float bh = expf(hv) * ah;
                float Hf = (float)H;
                float X = __fdiv_rn(x + (float)cx, Hf);
                float Y = __fdiv_rn(y + (float)cy, Hf);
                g_bbox[gw] = make_float4(X - bw * 0.5f, Y - bh * 0.5f,
                                         X + bw * 0.5f, Y + bh * 0.5f);
                g_conf[gw] = obj;
                g_cls[gw]  = bi;
            }
        }
        if (lane == 0) { s_mx[wid] = runM; s_mn[wid] = runm; }
        __syncthreads();
        if (tid == 0) {
            float M = s_mx[0], m = s_mn[0];
            #pragma unroll
            for (int i = 1; i < 32; ++i) { M = fmaxf(M, s_mx[i]); m = fminf(m, s_mn[i]); }
            atomicMax(&g_maxp, enc_ord(M));
            atomicMin(&g_minp, enc_ord(m));
        }
    }
    gridbar(++bk);

    // ================= P1: keys + pass-0 histogram =================
    {
        unsigned* h = (unsigned*)SB;
        for (int i = tid; i < 256; i += NTHR) h[i] = 0u;
        __syncthreads();
        float M = dec_ord(g_maxp);
        float m = dec_ord(g_minp);
        int p = b * SEG + tid;
        if (tid < SEG && p < NTOT) {
            float c = g_conf[p];
            float score = fmaxf(c * M, c * m);
            unsigned key = (score > 0.0f) ? ~enc_ord(score) : 0xFFFFFFFFu;
            g_keysA[p] = key;
            g_valsA[p] = (unsigned)p;
            atomicAdd(&h[key & 0xFFu], 1u);
        }
        __syncthreads();
        for (int i = tid; i < 256; i += NTHR) g_counts[i * NBLK + b] = h[i];
    }
    gridbar(++bk);

    // ================= P2: 4x8-bit LSD radix sort =================
    for (int pass = 0; pass < 4; ++pass) {
        const unsigned* kin = (pass & 1) ? g_keysB : g_keysA;
        const unsigned* vin = (pass & 1) ? g_valsB : g_valsA;
        unsigned* kout = (pass & 1) ? g_keysA : g_keysB;
        unsigned* vout = (pass & 1) ? g_valsA : g_valsB;

        if (pass > 0) {
            unsigned* h = (unsigned*)SB;
            for (int i = tid; i < 256; i += NTHR) h[i] = 0u;
            __syncthreads();
            int p = b * SEG + tid;
            if (tid < SEG && p < NTOT)
                atomicAdd(&h[(kin[p] >> (pass * 8)) & 0xFFu], 1u);
            __syncthreads();
            for (int i = tid; i < 256; i += NTHR) g_counts[i * NBLK + b] = h[i];
            gridbar(++bk);
        }

        // scan (block 0 only)
        if (b == 0) {
            unsigned* tot = (unsigned*)SB;
            if (tid < 256) {
                unsigned run = 0;
                for (int t = 0; t < NBLK; ++t) {
                    unsigned c = g_counts[tid * NBLK + t];
                    g_counts[tid * NBLK + t] = run;
                    run += c;
                }
                tot[tid] = run;
            }
            __syncthreads();
            for (int off = 1; off < 256; off <<= 1) {
                unsigned v = 0;
                if (tid < 256) v = tot[tid] + ((tid >= off) ? tot[tid - off] : 0u);
                __syncthreads();
                if (tid < 256) tot[tid] = v;
                __syncthreads();
            }
            if (tid < 256) g_digitbase[tid] = (tid == 0) ? 0u : tot[tid - 1];
        }
        gridbar(++bk);

        // scatter
        {
            unsigned (*wc)[256] = (unsigned (*)[256])SB;  // 31 warps used
            for (int i = tid; i < 31 * 256; i += NTHR) ((unsigned*)wc)[i] = 0u;
            __syncthreads();
            int p = b * SEG + tid;
            bool valid = (tid < SEG && p < NTOT);
            unsigned key = valid ? kin[p] : 0u;
            unsigned d = (key >> (pass * 8)) & 0xFFu;
            unsigned vmask = __ballot_sync(0xffffffffu, valid);
            unsigned mask  = __match_any_sync(0xffffffffu, d) & vmask;
            unsigned lr    = __popc(mask & ((1u << lane) - 1u));
            if (valid && lr == 0) wc[wid][d] = __popc(mask);
            __syncthreads();
            if (tid < 256) {
                unsigned run = 0;
                #pragma unroll
                for (int ww = 0; ww < 31; ++ww) {
                    unsigned c = wc[ww][tid];
                    wc[ww][tid] = run;
                    run += c;
                }
            }
            __syncthreads();
            if (valid) {
                unsigned dst = g_digitbase[d] + g_counts[d * NBLK + b] + wc[wid][d] + lr;
                kout[dst] = key;
                vout[dst] = vin[p];
            }
        }
        gridbar(++bk);
    }

    // ================= P3: NMS + output (block 0 only) =================
    if (b != 0) return;

    float4* candBox   = (float4*)(SB);              // 16384
    float*  candArea  = (float*)(SB + 16384);       // 4096
    float*  candScore = (float*)(SB + 20480);       // 4096
    int*    candIdx   = (int*)(SB + 24576);         // 4096
    float4* selBox    = (float4*)(SB + 28672);      // 1600
    float*  selArea   = (float*)(SB + 30272);       // 400
    float*  selScore  = (float*)(SB + 30672);       // 400
    int*    selIdx    = (int*)(SB + 31072);         // 400

    if (tid == 0) { s_nsel = 0; s_done = 0; s_hitEnd = 0; }
    __syncthreads();

    for (int pos = 0; pos < NTOT; pos += NTHR) {
        __syncthreads();

        int p = pos + tid;
        bool ok = false;
        float4 mybox = make_float4(0.f, 0.f, 0.f, 0.f);
        float myarea = 0.f, myscore = 0.f;
        int myidx = 0;

        if (p < NTOT) {
            unsigned k = g_keysA[p];
            if (k == 0xFFFFFFFFu) {
                s_hitEnd = 1;
            } else {
                myidx = (int)g_valsA[p];
                mybox = g_bbox[myidx];
                myarea = (mybox.z - mybox.x) * (mybox.w - mybox.y);
                myscore = dec_ord(~k);
                ok = true;
                int n0 = s_nsel;
                for (int s = 0; s < n0; ++s) {
                    if (iou_gt_half(mybox, myarea, selBox[s], selArea[s])) { ok = false; break; }
                }
            }
        } else {
            s_hitEnd = 1;
        }

        candBox[tid] = mybox;
        candArea[tid] = myarea;
        candScore[tid] = myscore;
        candIdx[tid] = myidx;
        bool myAlive = ok;
        __syncthreads();

        while (true) {
            unsigned bal = __ballot_sync(0xffffffffu, myAlive);
            if (lane == 0) s_ball[wid] = bal;
            __syncthreads();
            if (tid == 0) {
                int first = -1;
                for (int ww = 0; ww < 32; ++ww) {
                    unsigned bb = s_ball[ww];
                    if (bb) { first = (ww << 5) + __ffs(bb) - 1; break; }
                }
                s_first = first;
                if (first >= 0) {
                    int n = s_nsel;
                    selBox[n]   = candBox[first];
                    selArea[n]  = candArea[first];
                    selScore[n] = candScore[first];
                    selIdx[n]   = candIdx[first];
                    s_nsel = n + 1;
                    if (n + 1 >= MAXB) s_done = 1;
                }
            }
            __syncthreads();
            int first = s_first;
            if (first < 0) break;
            if (myAlive) {
                if (iou_gt_half(mybox, myarea, candBox[first], candArea[first]))
                    myAlive = false;
            }
            if (s_done) break;
            __syncthreads();
        }

        if (s_done || s_hitEnd) break;
    }

    __syncthreads();
    int nsel = s_nsel;
    for (int i = tid; i < out_size; i += NTHR) {
        float v = 0.0f;
        if (i < 400) {
            int j = i >> 2;
            if (j < nsel) v = ((float*)selBox)[i];
        } else if (i < 500) {
            int j = i - 400;
            if (j < nsel) v = selScore[j];
        } else if (i < 600) {
            int j = i - 500;
            if (j < nsel) v = (float)g_cls[selIdx[j]];
        } else if (i == 600) {
            v = (float)nsel;
        }
        out[i] = v;
    }
}

// ---------------- launch ----------------
extern "C" void kernel_launch(void* const* d_in, const int* in_sizes, int n_in,
                              void* d_out, int out_size) {
    const float* g0   = (const float*)d_in[0];
    const float* g1   = (const float*)d_in[1];
    const float* g2   = (const float*)d_in[2];
    const float* anch = (const float*)d_in[3];
    float* out = (float*)d_out;

    reset_kernel<<<1, 1>>>();
    mega_kernel<<<NBLK, NTHR>>>(g0, g1, g2, anch, out, out_size);
}

// round 3
// speedup vs baseline: 1.4597x; 1.1230x over previous
#include <cuda_runtime.h>
#include <cuda_bf16.h>

// ---------------- problem constants ----------------
#define N0 6912      // 48*48*3
#define N1 27648     // 96*96*3
#define N2 110592    // 192*192*3
#define NTOT 145152
#define NBLK 148
#define NTHR 1024
#define MAXB 100
#define CCAP 6144
#define STARGET 4096u
#define DSBYTES 196608   // dynamic smem: k0,v0,k1,v1 (24KB each) + boxes (96KB)

// ---------------- scratch (device globals) ----------------
__device__ float4   g_bbox[NTOT];
__device__ float    g_conf[NTOT];
__device__ int      g_cls[NTOT];
__device__ unsigned g_keysA[NTOT];
__device__ unsigned g_hist16[65536];
__device__ unsigned g_candK[CCAP], g_candV[CCAP];
__device__ unsigned g_maxp, g_minp, g_ticket, g_overflow;
__device__ unsigned g_barcnt, g_barrel;

// order-preserving float<->uint encodings
__device__ __forceinline__ unsigned enc_ord(float f) {
    unsigned u = __float_as_uint(f);
    return (u & 0x80000000u) ? ~u : (u ^ 0x80000000u);
}
__device__ __forceinline__ float dec_ord(unsigned o) {
    unsigned u = (o & 0x80000000u) ? (o ^ 0x80000000u) : ~o;
    return __uint_as_float(u);
}

__device__ __forceinline__ bool iou_gt_half(float4 a, float areaA, float4 b, float areaB) {
    float iw = fminf(a.z, b.z) - fmaxf(a.x, b.x); iw = fmaxf(iw, 0.0f);
    float ih = fminf(a.w, b.w) - fmaxf(a.y, b.y); ih = fmaxf(ih, 0.0f);
    float inter = iw * ih;
    float iou = __fdiv_rn(inter, areaA + areaB - inter);
    return iou > 0.5f;
}

// ---------------- grid barrier ----------------
__device__ __forceinline__ void gridbar(unsigned k) {
    __syncthreads();
    if (threadIdx.x == 0) {
        __threadfence();
        unsigned v = atomicAdd(&g_barcnt, 1u);
        if (v + 1u == k * (unsigned)NBLK) {
            __threadfence();
            atomicExch(&g_barrel, k);
        } else {
            unsigned r;
            do {
                asm volatile("ld.acquire.gpu.u32 %0, [%1];" : "=r"(r) : "l"(&g_barrel) : "memory");
            } while (r < k);
        }
    }
    __syncthreads();
}

// ---------------- K0: reset ----------------
__global__ void reset_kernel() {
    g_barcnt = 0u;
    g_barrel = 0u;
    g_maxp = 0u;
    g_minp = 0xFFFFFFFFu;
    g_ticket = 0u;
    g_overflow = 0u;
}

// ---------------- K1: persistent mega kernel ----------------
__global__ void __launch_bounds__(NTHR, 1)
mega_kernel(const float* __restrict__ g0,
            const float* __restrict__ g1,
            const float* __restrict__ g2,
            const float* __restrict__ anch,
            float* __restrict__ out, int out_size) {
    extern __shared__ unsigned char DS[];
    unsigned* k0 = (unsigned*)DS;                       // 24576
    unsigned* v0 = (unsigned*)(DS + 24576);
    unsigned* k1 = (unsigned*)(DS + 49152);
    unsigned* v1 = (unsigned*)(DS + 73728);
    float4*  boxes = (float4*)(DS + 98304);             // 98304 bytes
    unsigned (*wc)[256] = (unsigned (*)[256])(DS + 98304);  // alias of boxes (sort only)
    unsigned* s_scan = (unsigned*)DS;                   // alias of k0 (cutoff phase only)

    __shared__ float s_mx[32], s_mn[32];
    __shared__ unsigned s_hb[256], s_rb[256];
    __shared__ int s_cstar;
    __shared__ int s_opos[MAXB];
    __shared__ float4 o_box[MAXB];
    __shared__ float  o_score[MAXB];
    __shared__ int    o_cls[MAXB];
    __shared__ int s_nsel, s_nties;

    const int tid  = threadIdx.x;
    const int b    = blockIdx.x;
    const int lane = tid & 31;
    const int wid  = tid >> 5;
    unsigned bk = 0;

    // ================= P0: zero histogram + decode =================
    for (int i = b * NTHR + tid; i < 65536; i += NBLK * NTHR) g_hist16[i] = 0u;
    {
        float runM = -3.4e38f, runm = 3.4e38f;
        for (int gw = b * 32 + wid; gw < NTOT; gw += NBLK * 32) {
            const float* src; int H; int local; int abase;
            if (gw < N0)           { src = g0; H = 48;  local = gw;           abase = 12; }
            else if (gw < N0 + N1) { src = g1; H = 96;  local = gw - N0;      abase = 6;  }
            else                   { src = g2; H = 192; local = gw - N0 - N1; abase = 0;  }
            const float* p = src + (size_t)local * 85;

            float bv = -3.4e38f;
            int bi = 0;
            for (int c = lane; c < 80; c += 32) {
                float v = p[5 + c];
                if (v > bv) { bv = v; bi = c; }
            }
            #pragma unroll
            for (int off = 16; off; off >>= 1) {
                float ov = __shfl_xor_sync(0xffffffffu, bv, off);
                int   oi = __shfl_xor_sync(0xffffffffu, bi, off);
                if (ov > bv || (ov == bv && oi < bi)) { bv = ov; bi = oi; }
            }
            runM = fmaxf(runM, bv);
            runm = fminf(runm, bv);

            if (lane == 0) {
                float x = p[0], y = p[1], wv = p[2], hv = p[3], obj = p[4];
                int a = local % 3;
                int cell = local / 3;
                int cx = cell % H;   // W == H
                int cy = cell / H;
                float aw = anch[abase + a * 2 + 0];
                float ah = anch[abase + a * 2 + 1];
                float bw = expf(wv) * aw;
                float bh = expf(hv) * ah;
                float Hf = (float)H;
                float X = __fdiv_rn(x + (float)cx, Hf);
                float Y = __fdiv_rn(y + (float)cy, Hf);
                g_bbox[gw] = make_float4(X - bw * 0.5f, Y - bh * 0.5f,
                                         X + bw * 0.5f, Y + bh * 0.5f);
                g_conf[gw] = obj;
                g_cls[gw]  = bi;
            }
        }
        if (lane == 0) { s_mx[wid] = runM; s_mn[wid] = runm; }
        __syncthreads();
        if (tid == 0) {
            float M = s_mx[0], m = s_mn[0];
            #pragma unroll
            for (int i = 1; i < 32; ++i) { M = fmaxf(M, s_mx[i]); m = fminf(m, s_mn[i]); }
            atomicMax(&g_maxp, enc_ord(M));
            atomicMin(&g_minp, enc_ord(m));
        }
    }
    gridbar(++bk);

    // ================= P1: keys + 16-bit histogram =================
    {
        float M = dec_ord(g_maxp);
        float m = dec_ord(g_minp);
        for (int i = b * NTHR + tid; i < NTOT; i += NBLK * NTHR) {
            float c = g_conf[i];
            float score = fmaxf(c * M, c * m);
            unsigned key = (score > 0.0f) ? ~enc_ord(score) : 0xFFFFFFFFu;
            g_keysA[i] = key;
            atomicAdd(&g_hist16[key >> 16], 1u);
        }
    }
    gridbar(++bk);

    // ================= P2: find cutoff (every block, redundantly) =================
    unsigned totalvalid;
    int cstar;
    {
        unsigned part = 0;
        int base = tid * 64;
        #pragma unroll 8
        for (int i = 0; i < 64; ++i) part += g_hist16[base + i];
        s_scan[tid] = part;
        __syncthreads();
        unsigned x = part;
        for (int off = 1; off < 1024; off <<= 1) {
            unsigned add = (tid >= off) ? s_scan[tid - off] : 0u;
            __syncthreads();
            x += add;
            s_scan[tid] = x;
            __syncthreads();
        }
        totalvalid = s_scan[511];   // bins 0x0000..0x7FFF = valid (score>0)
        unsigned S = STARGET < totalvalid ? STARGET : totalvalid;
        if (tid == 0) s_cstar = -1;
        __syncthreads();
        if (S > 0 && tid < 512) {
            unsigned prev = (tid == 0) ? 0u : s_scan[tid - 1];
            if (x >= S && prev < S) {
                unsigned run = prev;
                for (int i = 0; i < 64; ++i) {
                    run += g_hist16[base + i];
                    if (run >= S) { s_cstar = base + i; break; }
                }
            }
        }
        __syncthreads();
        cstar = s_cstar;
    }

    // ================= P3: compaction =================
    if (cstar >= 0) {
        for (int i = b * NTHR + tid; i < NTOT; i += NBLK * NTHR) {
            unsigned key = g_keysA[i];
            if ((int)(key >> 16) <= cstar) {
                unsigned pos = atomicAdd(&g_ticket, 1u);
                if (pos < CCAP) { g_candK[pos] = key; g_candV[pos] = (unsigned)i; }
                else            { g_overflow = 1u; }
            }
        }
    }
    gridbar(++bk);

    if (b != 0) return;

    // ================= block 0: sort + NMS + output =================
    int C = (int)(g_ticket < (unsigned)CCAP ? g_ticket : (unsigned)CCAP);
    int ovf = (int)g_overflow;

    if (tid == 0) { s_nsel = 0; s_nties = 0; }
    __syncthreads();

    if (C > 0) {
        int nwv = (C + 1023) >> 10;
        int NP = nwv << 10;
        for (int i = tid; i < NP; i += NTHR) {
            if (i < C) { k0[i] = g_candK[i]; v0[i] = g_candV[i]; }
            else       { k0[i] = 0xFFFFFFFFu; v0[i] = 0xFFFFFFFFu; }
        }
        __syncthreads();

        // ---- 4x8-bit stable LSD radix sort in smem ----
        for (int pass = 0; pass < 4; ++pass) {
            unsigned* sk = (pass & 1) ? k1 : k0;
            unsigned* sv = (pass & 1) ? v1 : v0;
            unsigned* dk = (pass & 1) ? k0 : k1;
            unsigned* dv = (pass & 1) ? v0 : v1;
            int sh = pass * 8;

            if (tid < 256) s_hb[tid] = 0u;
            __syncthreads();
            for (int i = tid; i < NP; i += NTHR)
                atomicAdd(&s_hb[(sk[i] >> sh) & 255u], 1u);
            __syncthreads();

            unsigned x = (tid < 256) ? s_hb[tid] : 0u;
            unsigned cnt = x;
            for (int off = 1; off < 256; off <<= 1) {
                unsigned add = (tid < 256 && tid >= off) ? s_hb[tid - off] : 0u;
                __syncthreads();
                if (tid < 256) { x += add; s_hb[tid] = x; }
                __syncthreads();
            }
            if (tid < 256) s_rb[tid] = x - cnt;   // exclusive base
            __syncthreads();

            for (int w = 0; w < nwv; ++w) {
                for (int j = tid; j < 32 * 256; j += NTHR) ((unsigned*)wc)[j] = 0u;
                __syncthreads();
                int e = (w << 10) + tid;
                unsigned key = sk[e];
                unsigned d = (key >> sh) & 255u;
                unsigned mask = __match_any_sync(0xffffffffu, d);
                unsigned lr = __popc(mask & ((1u << lane) - 1u));
                if (lr == 0) wc[wid][d] = __popc(mask);
                __syncthreads();
                if (tid < 256) {
                    unsigned run = s_rb[tid];
                    #pragma unroll
                    for (int ww = 0; ww < 32; ++ww) {
                        unsigned c2 = wc[ww][tid];
                        wc[ww][tid] = run;
                        run += c2;
                    }
                    s_rb[tid] = run;
                }
                __syncthreads();
                unsigned dst = wc[wid][d] + lr;
                dk[dst] = key;
                dv[dst] = sv[e];
                __syncthreads();
            }
        }
        // result in k0/v0

        // ---- exact tie-break: equal keys -> ascending idx ----
        for (int i = tid; i < C; i += NTHR)
            if (i > 0 && k0[i] == k0[i - 1]) atomicAdd(&s_nties, 1);
        __syncthreads();
        if (s_nties) {
            for (int i = tid; i < C; i += NTHR) {
                if ((i == 0 || k0[i] != k0[i - 1]) && i + 1 < C && k0[i + 1] == k0[i]) {
                    int j = i + 1;
                    while (j < C && k0[j] == k0[i]) j++;
                    for (int a = i + 1; a < j; ++a) {
                        unsigned val = v0[a];
                        int p = a - 1;
                        while (p >= i && v0[p] > val) { v0[p + 1] = v0[p]; --p; }
                        v0[p + 1] = val;
                    }
                }
            }
        }
        __syncthreads();

        // ---- load candidate boxes into smem ----
        for (int i = tid; i < C; i += NTHR) boxes[i] = g_bbox[v0[i]];
        __syncthreads();

        // ---- warp-serial greedy NMS (warp 0; selected in lane registers) ----
        if (wid == 0) {
            float4 s0b = make_float4(0,0,0,0), s1b = s0b, s2b = s0b, s3b = s0b;
            float s0a = 0.f, s1a = 0.f, s2a = 0.f, s3a = 0.f;
            int nsel = 0;
            for (int i = 0; i < C && nsel < MAXB; ++i) {
                float4 bx = boxes[i];
                float ar = (bx.z - bx.x) * (bx.w - bx.y);
                bool sup = false;
                if (lane      < nsel) sup |= iou_gt_half(bx, ar, s0b, s0a);
                if (lane + 32 < nsel) sup |= iou_gt_half(bx, ar, s1b, s1a);
                if (lane + 64 < nsel) sup |= iou_gt_half(bx, ar, s2b, s2a);
                if (lane + 96 < nsel) sup |= iou_gt_half(bx, ar, s3b, s3a);
                if (!__any_sync(0xffffffffu, sup)) {
                    int kk = nsel >> 5, ll = nsel & 31;
                    if (lane == ll) {
                        if      (kk == 0) { s0b = bx; s0a = ar; }
                        else if (kk == 1) { s1b = bx; s1a = ar; }
                        else if (kk == 2) { s2b = bx; s2a = ar; }
                        else              { s3b = bx; s3a = ar; }
                    }
                    if (lane == 0) s_opos[nsel] = i;
                    nsel++;
                }
            }
            if (lane == 0) s_nsel = nsel;
        }
        __syncthreads();

        // ---- fill output arrays (fast path) ----
        int ns = s_nsel;
        for (int j = tid; j < ns; j += NTHR) {
            int i = s_opos[j];
            o_box[j]   = boxes[i];
            o_score[j] = dec_ord(~k0[i]);
            o_cls[j]   = g_cls[v0[i]];
        }
        __syncthreads();
    }

    // ================= fallback (exactness guard; normally never taken) =================
    {
        bool need_fb = (s_nsel < MAXB) && (ovf || totalvalid > (unsigned)C);
        if (need_fb) {
            if (tid == 0) s_nsel = 0;
            __syncthreads();
            unsigned long long* red = (unsigned long long*)k1;
            for (int r = 0; r < MAXB; ++r) {
                unsigned long long best = ~0ull;
                for (int i = tid; i < NTOT; i += NTHR) {
                    unsigned k = g_keysA[i];
                    if (k < 0x80000000u) {
                        unsigned long long cmp = ((unsigned long long)k << 32) | (unsigned)i;
                        if (cmp < best) best = cmp;
                    }
                }
                red[tid] = best;
                __syncthreads();
                for (int off = 512; off; off >>= 1) {
                    if (tid < off && red[tid + off] < red[tid]) red[tid] = red[tid + off];
                    __syncthreads();
                }
                best = red[0];
                __syncthreads();
                if (best == ~0ull) break;
                unsigned j = (unsigned)(best & 0xFFFFFFFFu);
                float4 bj = g_bbox[j];
                float aj = (bj.z - bj.x) * (bj.w - bj.y);
                if (tid == 0) {
                    int n = s_nsel;
                    o_box[n]   = bj;
                    o_score[n] = dec_ord(~(unsigned)(best >> 32));
                    o_cls[n]   = g_cls[j];
                    s_nsel = n + 1;
                }
                for (int i = tid; i < NTOT; i += NTHR) {
                    unsigned k = g_keysA[i];
                    if (k < 0x80000000u) {
                        float4 bi = g_bbox[i];
                        float ai = (bi.z - bi.x) * (bi.w - bi.y);
                        if (iou_gt_half(bi, ai, bj, aj)) g_keysA[i] = 0xFFFFFFFFu;
                    }
                }
                __syncthreads();
            }
        }
    }
    __syncthreads();

    // ================= output =================
    int ns = s_nsel;
    for (int i = tid; i < out_size; i += NTHR) {
        float v = 0.0f;
        if (i < 400) {
            int j = i >> 2;
            if (j < ns) v = ((float*)o_box)[i];
        } else if (i < 500) {
            int j = i - 400;
            if (j < ns) v = o_score[j];
        } else if (i < 600) {
            int j = i - 500;
            if (j < ns) v = (float)o_cls[j];
        } else if (i == 600) {
            v = (float)ns;
        }
        out[i] = v;
    }
}

// ---------------- launch ----------------
extern "C" void kernel_launch(void* const* d_in, const int* in_sizes, int n_in,
                              void* d_out, int out_size) {
    const float* g0   = (const float*)d_in[0];
    const float* g1   = (const float*)d_in[1];
    const float* g2   = (const float*)d_in[2];
    const float* anch = (const float*)d_in[3];
    float* out = (float*)d_out;

    cudaFuncSetAttribute(mega_kernel, cudaFuncAttributeMaxDynamicSharedMemorySize, DSBYTES);
    reset_kernel<<<1, 1>>>();
    mega_kernel<<<NBLK, NTHR, DSBYTES>>>(g0, g1, g2, anch, out, out_size);
}

// round 4
// speedup vs baseline: 2.1053x; 1.4423x over previous
#include <cuda_runtime.h>
#include <cuda_bf16.h>

// ---------------- problem constants ----------------
#define N0 6912      // 48*48*3
#define N1 27648     // 96*96*3
#define N2 110592    // 192*192*3
#define NTOT 145152
#define NBLK 148
#define NTHR 1024
#define MAXB 100
#define CCAP 4096
#define STARGET 1900u
#define TW 36288      // total warps in K1 (NTOT/4)
#define K1BLK 2268    // TW/16
#define DSBYTES 131072

// ---------------- scratch (device globals) ----------------
__device__ float    g_conf[NTOT];
__device__ unsigned g_keysA[NTOT];
__device__ unsigned g_hist16[65536];
__device__ unsigned g_candK[CCAP], g_candV[CCAP];
__device__ float4   g_candBox[CCAP];
__device__ int      g_candCls[CCAP];
__device__ float4   g_bboxFB[NTOT];   // fallback-only scratch
__device__ unsigned g_maxp, g_minp, g_ticket, g_overflow;
__device__ unsigned g_barcnt, g_barrel;

// order-preserving float<->uint encodings
__device__ __forceinline__ unsigned enc_ord(float f) {
    unsigned u = __float_as_uint(f);
    return (u & 0x80000000u) ? ~u : (u ^ 0x80000000u);
}
__device__ __forceinline__ float dec_ord(unsigned o) {
    unsigned u = (o & 0x80000000u) ? (o ^ 0x80000000u) : ~o;
    return __uint_as_float(u);
}

__device__ __forceinline__ bool iou_gt_half(float4 a, float areaA, float4 b, float areaB) {
    float iw = fminf(a.z, b.z) - fmaxf(a.x, b.x); iw = fmaxf(iw, 0.0f);
    float ih = fminf(a.w, b.w) - fmaxf(a.y, b.y); ih = fmaxf(ih, 0.0f);
    float inter = iw * ih;
    float iou = __fdiv_rn(inter, areaA + areaB - inter);
    return iou > 0.5f;
}

__device__ __forceinline__ const float* box_ptr(int gw,
        const float* g0, const float* g1, const float* g2,
        int& H, int& abase, int& local) {
    if (gw < N0)      { H = 48;  abase = 12; local = gw;           return g0 + (size_t)local * 85; }
    if (gw < N0 + N1) { H = 96;  abase = 6;  local = gw - N0;      return g1 + (size_t)local * 85; }
    H = 192; abase = 0; local = gw - N0 - N1; return g2 + (size_t)local * 85;
}

__device__ __forceinline__ float4 geom(const float* p, int local, int H, int abase,
                                       const float* anch) {
    float x = p[0], y = p[1], wv = p[2], hv = p[3];
    int a = local % 3;
    int cell = local / 3;
    int cx = cell % H;   // W == H
    int cy = cell / H;
    float aw = anch[abase + a * 2 + 0];
    float ah = anch[abase + a * 2 + 1];
    float bw = expf(wv) * aw;
    float bh = expf(hv) * ah;
    float Hf = (float)H;
    float X = __fdiv_rn(x + (float)cx, Hf);
    float Y = __fdiv_rn(y + (float)cy, Hf);
    return make_float4(X - bw * 0.5f, Y - bh * 0.5f, X + bw * 0.5f, Y + bh * 0.5f);
}

// ---------------- grid barrier ----------------
__device__ __forceinline__ void gridbar(unsigned k) {
    __syncthreads();
    if (threadIdx.x == 0) {
        __threadfence();
        unsigned v = atomicAdd(&g_barcnt, 1u);
        if (v + 1u == k * (unsigned)NBLK) {
            __threadfence();
            atomicExch(&g_barrel, k);
        } else {
            unsigned r;
            do {
                asm volatile("ld.acquire.gpu.u32 %0, [%1];" : "=r"(r) : "l"(&g_barrel) : "memory");
            } while (r < k);
        }
    }
    __syncthreads();
}

// ---------------- K0: reset ----------------
__global__ void reset_kernel() {
    g_barcnt = 0u;
    g_barrel = 0u;
    g_maxp = 0u;
    g_minp = 0xFFFFFFFFu;
    g_ticket = 0u;
    g_overflow = 0u;
}

// ---------------- K1: streaming conf + M/m reduction ----------------
__global__ void __launch_bounds__(512)
k1_kernel(const float* __restrict__ g0,
          const float* __restrict__ g1,
          const float* __restrict__ g2) {
    int tid = threadIdx.x;
    int lane = tid & 31;
    int wid = tid >> 5;

    unsigned gtid = blockIdx.x * 512u + (unsigned)tid;
    if (gtid < 65536u) g_hist16[gtid] = 0u;

    int w = blockIdx.x * 16 + wid;   // 0..TW-1
    float bv[4], cf[4];

    #pragma unroll
    for (int it = 0; it < 4; ++it) {
        int gw = w + it * TW;
        int H, abase, local;
        const float* p = box_ptr(gw, g0, g1, g2, H, abase, local);
        float v0 = p[5 + lane];
        float v1 = p[37 + lane];
        float v2 = (lane < 16) ? p[69 + lane] : -3.4e38f;
        bv[it] = fmaxf(fmaxf(v0, v1), v2);
        cf[it] = (lane == 0) ? p[4] : 0.0f;
    }
    #pragma unroll
    for (int it = 0; it < 4; ++it) {
        #pragma unroll
        for (int off = 16; off; off >>= 1)
            bv[it] = fmaxf(bv[it], __shfl_xor_sync(0xffffffffu, bv[it], off));
    }
    if (lane == 0) {
        #pragma unroll
        for (int it = 0; it < 4; ++it) g_conf[w + it * TW] = cf[it];
    }

    float M = fmaxf(fmaxf(bv[0], bv[1]), fmaxf(bv[2], bv[3]));
    float m = fminf(fminf(bv[0], bv[1]), fminf(bv[2], bv[3]));
    __shared__ float sM[16], sm[16];
    if (lane == 0) { sM[wid] = M; sm[wid] = m; }
    __syncthreads();
    if (tid == 0) {
        #pragma unroll
        for (int i = 1; i < 16; ++i) { M = fmaxf(M, sM[i]); m = fminf(m, sm[i]); }
        atomicMax(&g_maxp, enc_ord(M));
        atomicMin(&g_minp, enc_ord(m));
    }
}

// ---------------- K2: keys -> top-K -> candidate decode -> sort -> NMS ----------------
__global__ void __launch_bounds__(NTHR, 1)
k2_kernel(const float* __restrict__ g0,
          const float* __restrict__ g1,
          const float* __restrict__ g2,
          const float* __restrict__ anch,
          float* __restrict__ out, int out_size) {
    extern __shared__ unsigned char DS[];
    unsigned* ka = (unsigned*)DS;                       // 16384
    unsigned* va = (unsigned*)(DS + 16384);
    unsigned* kb = (unsigned*)(DS + 32768);
    unsigned* vb = (unsigned*)(DS + 49152);
    float4*  sBox = (float4*)(DS + 65536);              // 65536 bytes
    unsigned (*wc)[256] = (unsigned (*)[256])(DS + 65536);  // alias (sort only)
    unsigned* s_scan = (unsigned*)DS;                   // alias of ka (cutoff only)

    __shared__ unsigned s_hb[256], s_rb[256];
    __shared__ int s_cstar;
    __shared__ int s_opos[MAXB];
    __shared__ int s_fbidx[MAXB];
    __shared__ float4 o_box[MAXB];
    __shared__ float  o_score[MAXB];
    __shared__ int    o_cls[MAXB];
    __shared__ int s_nsel, s_nties;

    const int tid  = threadIdx.x;
    const int b    = blockIdx.x;
    const int lane = tid & 31;
    const int wid  = tid >> 5;
    unsigned bk = 0;

    // ================= P1: keys + 16-bit histogram =================
    {
        float M = dec_ord(g_maxp);
        float m = dec_ord(g_minp);
        for (int i = b * NTHR + tid; i < NTOT; i += NBLK * NTHR) {
            float c = g_conf[i];
            float score = fmaxf(c * M, c * m);
            unsigned key = (score > 0.0f) ? ~enc_ord(score) : 0xFFFFFFFFu;
            g_keysA[i] = key;
            atomicAdd(&g_hist16[key >> 16], 1u);
        }
    }
    gridbar(++bk);

    // ================= P2: cutoff (redundant per block) + compaction =================
    unsigned totalvalid;
    int cstar;
    {
        unsigned part = 0;
        int base = tid * 64;
        #pragma unroll 8
        for (int i = 0; i < 64; ++i) part += g_hist16[base + i];
        s_scan[tid] = part;
        __syncthreads();
        unsigned x = part;
        for (int off = 1; off < 1024; off <<= 1) {
            unsigned add = (tid >= off) ? s_scan[tid - off] : 0u;
            __syncthreads();
            x += add;
            s_scan[tid] = x;
            __syncthreads();
        }
        totalvalid = s_scan[511];   // bins 0x0000..0x7FFF = valid (score>0)
        unsigned S = STARGET < totalvalid ? STARGET : totalvalid;
        if (tid == 0) s_cstar = -1;
        __syncthreads();
        if (S > 0 && tid < 512) {
            unsigned prev = (tid == 0) ? 0u : s_scan[tid - 1];
            if (x >= S && prev < S) {
                unsigned run = prev;
                for (int i = 0; i < 64; ++i) {
                    run += g_hist16[base + i];
                    if (run >= S) { s_cstar = base + i; break; }
                }
            }
        }
        __syncthreads();
        cstar = s_cstar;
    }
    if (cstar >= 0) {
        for (int i = b * NTHR + tid; i < NTOT; i += NBLK * NTHR) {
            unsigned key = g_keysA[i];
            if ((int)(key >> 16) <= cstar) {
                unsigned pos = atomicAdd(&g_ticket, 1u);
                if (pos < CCAP) { g_candK[pos] = key; g_candV[pos] = (unsigned)i; }
                else            { g_overflow = 1u; }
            }
        }
    }
    gridbar(++bk);

    // ================= P3: candidate decode (all blocks, warp per candidate) =================
    int C = (int)(g_ticket < (unsigned)CCAP ? g_ticket : (unsigned)CCAP);
    for (int idx = b * 32 + wid; idx < C; idx += NBLK * 32) {
        int gw = (int)g_candV[idx];
        int H, abase, local;
        const float* p = box_ptr(gw, g0, g1, g2, H, abase, local);

        float bvv = -3.4e38f;
        int bi = 0;
        for (int c = lane; c < 80; c += 32) {
            float v = p[5 + c];
            if (v > bvv) { bvv = v; bi = c; }
        }
        #pragma unroll
        for (int off = 16; off; off >>= 1) {
            float ov = __shfl_xor_sync(0xffffffffu, bvv, off);
            int   oi = __shfl_xor_sync(0xffffffffu, bi, off);
            if (ov > bvv || (ov == bvv && oi < bi)) { bvv = ov; bi = oi; }
        }
        if (lane == 0) {
            g_candBox[idx] = geom(p, local, H, abase, anch);
            g_candCls[idx] = bi;
        }
    }
    gridbar(++bk);

    if (b != 0) return;

    // ================= block 0: sort + NMS + output =================
    int ovf = (int)g_overflow;
    if (tid == 0) { s_nsel = 0; s_nties = 0; }
    __syncthreads();

    if (C > 0) {
        int nwv = (C + 1023) >> 10;
        int NP = nwv << 10;
        for (int i = tid; i < NP; i += NTHR) {
            if (i < C) { ka[i] = g_candK[i]; va[i] = (unsigned)i; }
            else       { ka[i] = 0xFFFFFFFFu; va[i] = 0u; }
        }
        __syncthreads();

        // ---- 4x8-bit stable LSD radix sort in smem ----
        for (int pass = 0; pass < 4; ++pass) {
            unsigned* sk = (pass & 1) ? kb : ka;
            unsigned* sv = (pass & 1) ? vb : va;
            unsigned* dk = (pass & 1) ? ka : kb;
            unsigned* dv = (pass & 1) ? va : vb;
            int sh = pass * 8;

            if (tid < 256) s_hb[tid] = 0u;
            __syncthreads();
            for (int i = tid; i < NP; i += NTHR)
                atomicAdd(&s_hb[(sk[i] >> sh) & 255u], 1u);
            __syncthreads();

            unsigned x = (tid < 256) ? s_hb[tid] : 0u;
            unsigned cnt = x;
            for (int off = 1; off < 256; off <<= 1) {
                unsigned add = (tid < 256 && tid >= off) ? s_hb[tid - off] : 0u;
                __syncthreads();
                if (tid < 256) { x += add; s_hb[tid] = x; }
                __syncthreads();
            }
            if (tid < 256) s_rb[tid] = x - cnt;   // exclusive base
            __syncthreads();

            for (int w = 0; w < nwv; ++w) {
                for (int j = tid; j < 32 * 256; j += NTHR) ((unsigned*)wc)[j] = 0u;
                __syncthreads();
                int e = (w << 10) + tid;
                unsigned key = sk[e];
                unsigned d = (key >> sh) & 255u;
                unsigned mask = __match_any_sync(0xffffffffu, d);
                unsigned lr = __popc(mask & ((1u << lane) - 1u));
                if (lr == 0) wc[wid][d] = __popc(mask);
                __syncthreads();
                if (tid < 256) {
                    unsigned run = s_rb[tid];
                    #pragma unroll
                    for (int ww = 0; ww < 32; ++ww) {
                        unsigned c2 = wc[ww][tid];
                        wc[ww][tid] = run;
                        run += c2;
                    }
                    s_rb[tid] = run;
                }
                __syncthreads();
                unsigned dst = wc[wid][d] + lr;
                dk[dst] = key;
                dv[dst] = sv[e];
                __syncthreads();
            }
        }
        // result in ka/va (slots)

        // ---- exact tie-break: equal keys -> ascending original box idx ----
        for (int i = tid; i < C; i += NTHR)
            if (i > 0 && ka[i] == ka[i - 1]) atomicAdd(&s_nties, 1);
        __syncthreads();
        if (s_nties) {
            for (int i = tid; i < C; i += NTHR) {
                if ((i == 0 || ka[i] != ka[i - 1]) && i + 1 < C && ka[i + 1] == ka[i]) {
                    int j = i + 1;
                    while (j < C && ka[j] == ka[i]) j++;
                    for (int a = i + 1; a < j; ++a) {
                        unsigned slot = va[a];
                        unsigned key2 = g_candV[slot];
                        int p2 = a - 1;
                        while (p2 >= i && g_candV[va[p2]] > key2) { va[p2 + 1] = va[p2]; --p2; }
                        va[p2 + 1] = slot;
                    }
                }
            }
        }
        __syncthreads();

        // ---- gather candidate boxes in sorted order ----
        for (int i = tid; i < C; i += NTHR) sBox[i] = g_candBox[va[i]];
        __syncthreads();

        // ---- warp-serial greedy NMS (warp 0; selected boxes in lane registers) ----
        if (wid == 0) {
            float4 s0b = make_float4(0,0,0,0), s1b = s0b, s2b = s0b, s3b = s0b;
            float s0a = 0.f, s1a = 0.f, s2a = 0.f, s3a = 0.f;
            int nsel = 0;
            for (int i = 0; i < C && nsel < MAXB; ++i) {
                float4 bx = sBox[i];
                float ar = (bx.z - bx.x) * (bx.w - bx.y);
                bool sup = false;
                if (lane      < nsel) sup |= iou_gt_half(bx, ar, s0b, s0a);
                if (lane + 32 < nsel) sup |= iou_gt_half(bx, ar, s1b, s1a);
                if (lane + 64 < nsel) sup |= iou_gt_half(bx, ar, s2b, s2a);
                if (lane + 96 < nsel) sup |= iou_gt_half(bx, ar, s3b, s3a);
                if (!__any_sync(0xffffffffu, sup)) {
                    int kk = nsel >> 5, ll = nsel & 31;
                    if (lane == ll) {
                        if      (kk == 0) { s0b = bx; s0a = ar; }
                        else if (kk == 1) { s1b = bx; s1a = ar; }
                        else if (kk == 2) { s2b = bx; s2a = ar; }
                        else              { s3b = bx; s3a = ar; }
                    }
                    if (lane == 0) s_opos[nsel] = i;
                    nsel++;
                }
            }
            if (lane == 0) s_nsel = nsel;
        }
        __syncthreads();

        // ---- fill output arrays ----
        int ns = s_nsel;
        for (int j = tid; j < ns; j += NTHR) {
            int i = s_opos[j];
            o_box[j]   = sBox[i];
            o_score[j] = dec_ord(~ka[i]);
            o_cls[j]   = g_candCls[va[i]];
        }
        __syncthreads();
    }

    // ================= fallback (exactness guard; normally never taken) =================
    {
        bool need_fb = (s_nsel < MAXB) && (ovf || totalvalid > (unsigned)C);
        if (need_fb) {
            // decode all bboxes (block0 alone)
            for (int gw = tid; gw < NTOT; gw += NTHR) {
                int H, abase, local;
                const float* p = box_ptr(gw, g0, g1, g2, H, abase, local);
                g_bboxFB[gw] = geom(p, local, H, abase, anch);
            }
            if (tid == 0) s_nsel = 0;
            __syncthreads();
            unsigned long long* red = (unsigned long long*)kb;
            for (int r = 0; r < MAXB; ++r) {
                unsigned long long best = ~0ull;
                for (int i = tid; i < NTOT; i += NTHR) {
                    unsigned k = g_keysA[i];
                    if (k < 0x80000000u) {
                        unsigned long long cmp = ((unsigned long long)k << 32) | (unsigned)i;
                        if (cmp < best) best = cmp;
                    }
                }
                red[tid] = best;
                __syncthreads();
                for (int off = 512; off; off >>= 1) {
                    if (tid < off && red[tid + off] < red[tid]) red[tid] = red[tid + off];
                    __syncthreads();
                }
                best = red[0];
                __syncthreads();
                if (best == ~0ull) break;
                unsigned j = (unsigned)(best & 0xFFFFFFFFu);
                float4 bj = g_bboxFB[j];
                float aj = (bj.z - bj.x) * (bj.w - bj.y);
                if (tid == 0) {
                    int n = s_nsel;
                    o_box[n]   = bj;
                    o_score[n] = dec_ord(~(unsigned)(best >> 32));
                    s_fbidx[n] = (int)j;
                    s_nsel = n + 1;
                }
                for (int i = tid; i < NTOT; i += NTHR) {
                    unsigned k = g_keysA[i];
                    if (k < 0x80000000u) {
                        float4 bi = g_bboxFB[i];
                        float ai = (bi.z - bi.x) * (bi.w - bi.y);
                        if (iou_gt_half(bi, ai, bj, aj)) g_keysA[i] = 0xFFFFFFFFu;
                    }
                }
                __syncthreads();
            }
            // classes for fallback selections (serial argmax per selection)
            for (int j2 = tid; j2 < s_nsel; j2 += NTHR) {
                int gw = s_fbidx[j2];
                int H, abase, local;
                const float* p = box_ptr(gw, g0, g1, g2, H, abase, local);
                float bestv = -3.4e38f; int bi = 0;
                for (int c = 0; c < 80; ++c) {
                    float v = p[5 + c];
                    if (v > bestv) { bestv = v; bi = c; }
                }
                o_cls[j2] = bi;
            }
            __syncthreads();
        }
    }

    // ================= output =================
    int ns = s_nsel;
    for (int i = tid; i < out_size; i += NTHR) {
        float v = 0.0f;
        if (i < 400) {
            int j = i >> 2;
            if (j < ns) v = ((float*)o_box)[i];
        } else if (i < 500) {
            int j = i - 400;
            if (j < ns) v = o_score[j];
        } else if (i < 600) {
            int j = i - 500;
            if (j < ns) v = (float)o_cls[j];
        } else if (i == 600) {
            v = (float)ns;
        }
        out[i] = v;
    }
}

// ---------------- launch ----------------
extern "C" void kernel_launch(void* const* d_in, const int* in_sizes, int n_in,
                              void* d_out, int out_size) {
    const float* g0   = (const float*)d_in[0];
    const float* g1   = (const float*)d_in[1];
    const float* g2   = (const float*)d_in[2];
    const float* anch = (const float*)d_in[3];
    float* out = (float*)d_out;

    cudaFuncSetAttribute(k2_kernel, cudaFuncAttributeMaxDynamicSharedMemorySize, DSBYTES);
    reset_kernel<<<1, 1>>>();
    k1_kernel<<<K1BLK, 512>>>(g0, g1, g2);
    k2_kernel<<<NBLK, NTHR, DSBYTES>>>(g0, g1, g2, anch, out, out_size);
}